// round 14
// baseline (speedup 1.0000x reference)
#include <cuda_runtime.h>
#include <cuda_fp16.h>
#include <cstdint>
#include <math.h>

// ---------------- problem constants ----------------
#define B_SZ 16
#define H_SZ 8
#define L_SZ 1024
#define E_SZ 64
#define RS   512                 // floats between consecutive rows (H*E)

#define BM 128
#define BN 64
#define NT 16
#define THREADS 256

// ---------------- smem byte map (fp16 tiles, 128B swizzled rows) ------------
#define QO   0                       // 128 x 64 fp16 = 16 KB
#define KO(b) (16384 + (b) * 8192)   // 64 x 64 fp16, 4-slot ring
#define VO(b) (49152 + (b) * 8192)
#define SMEM_BYTES 81920

// precomputed tensors
__device__ __half g_kh[B_SZ * H_SZ * L_SZ * E_SZ];   // [bh][s][e] fp16
__device__ __half g_vh[B_SZ * H_SZ * L_SZ * E_SZ];
// g_wh[l][s] = fp16( softmax_s(wm[l][s]/softplus(tau[l])) * (1/8) * log2(e) )
__device__ __half g_wh[L_SZ * L_SZ];

// ---------------- helpers ----------------
__device__ __forceinline__ uint32_t smem_u32(const void* p) {
    uint32_t a;
    asm("{ .reg .u64 t; cvta.to.shared.u64 t, %1; cvt.u32.u64 %0, t; }" : "=r"(a) : "l"(p));
    return a;
}
// 128B-row XOR swizzle
__device__ __forceinline__ uint32_t swz(int r, int cb) {
    return (uint32_t)(r * 128 + (cb ^ ((r & 7) << 4)));
}
__device__ __forceinline__ float ex2f(float x) {
    float y; asm("ex2.approx.f32 %0, %1;" : "=f"(y) : "f"(x)); return y;
}

#define LDSM4(d0,d1,d2,d3,a) \
    asm volatile("ldmatrix.sync.aligned.m8n8.x4.shared.b16 {%0,%1,%2,%3}, [%4];" \
        : "=r"(d0),"=r"(d1),"=r"(d2),"=r"(d3) : "r"(a))
#define LDSM4T(d0,d1,d2,d3,a) \
    asm volatile("ldmatrix.sync.aligned.m8n8.x4.trans.shared.b16 {%0,%1,%2,%3}, [%4];" \
        : "=r"(d0),"=r"(d1),"=r"(d2),"=r"(d3) : "r"(a))
#define MMA16816(c, a0,a1,a2,a3, b0,b1) \
    asm volatile("mma.sync.aligned.m16n8k16.row.col.f32.f16.f16.f32 " \
        "{%0,%1,%2,%3},{%4,%5,%6,%7},{%8,%9},{%0,%1,%2,%3};" \
        : "+f"((c)[0]),"+f"((c)[1]),"+f"((c)[2]),"+f"((c)[3]) \
        : "r"(a0),"r"(a1),"r"(a2),"r"(a3),"r"(b0),"r"(b1))
#define CPA16(dst, src) \
    asm volatile("cp.async.cg.shared.global [%0], [%1], 16;" :: "r"(dst), "l"(src))
#define CPA_COMMIT() asm volatile("cp.async.commit_group;" ::: "memory")
#define CPA_WAIT0()  asm volatile("cp.async.wait_group 0;" ::: "memory")

__device__ __forceinline__ uint2 pack4h(float4 x) {
    half2 h0 = __floats2half2_rn(x.x, x.y);
    half2 h1 = __floats2half2_rn(x.z, x.w);
    return make_uint2(*(uint32_t*)&h0, *(uint32_t*)&h1);
}
__device__ __forceinline__ uint32_t pack2h(float a, float b) {
    half2 h = __floats2half2_rn(a, b);
    return *(uint32_t*)&h;
}

// ------- kernel 0: fused prep (K/V fp32->fp16 bh-major; w modulation) -------
__global__ void prep_kernel(const float* __restrict__ k, const float* __restrict__ v,
                            const float* __restrict__ wm, const float* __restrict__ tau) {
    if (blockIdx.x < 8192) {
        // K/V convert: one half4 per thread per tensor
        int o = blockIdx.x * 256 + threadIdx.x;      // half4 index, 2^21 total
        int e4 = o & 15;
        int s  = (o >> 4) & 1023;
        int bh = o >> 14;
        int b = bh >> 3, h = bh & 7;
        size_t in = (((size_t)b * L_SZ + s) * H_SZ + h) * 16 + e4;   // float4 units
        ((uint2*)g_kh)[o] = pack4h(((const float4*)k)[in]);
        ((uint2*)g_vh)[o] = pack4h(((const float4*)v)[in]);
        return;
    }
    // w modulation rows
    __shared__ float red_m[8];
    __shared__ float red_s[8];
    const int row = blockIdx.x - 8192, tid = threadIdx.x;
    const int warp = tid >> 5, lane = tid & 31;

    float t = tau[row];
    float sp = (t > 20.f) ? t : log1pf(__expf(t));
    float inv = 1.f / sp;

    float4 x = reinterpret_cast<const float4*>(wm + (size_t)row * L_SZ)[tid];
    x.x *= inv; x.y *= inv; x.z *= inv; x.w *= inv;

    float mx = fmaxf(fmaxf(x.x, x.y), fmaxf(x.z, x.w));
    #pragma unroll
    for (int o = 16; o; o >>= 1) mx = fmaxf(mx, __shfl_xor_sync(0xffffffffu, mx, o));
    if (lane == 0) red_m[warp] = mx;
    __syncthreads();
    float M = red_m[0];
    #pragma unroll
    for (int i = 1; i < 8; i++) M = fmaxf(M, red_m[i]);

    float e0 = __expf(x.x - M), e1 = __expf(x.y - M);
    float e2 = __expf(x.z - M), e3 = __expf(x.w - M);
    float s = e0 + e1 + e2 + e3;
    #pragma unroll
    for (int o = 16; o; o >>= 1) s += __shfl_xor_sync(0xffffffffu, s, o);
    if (lane == 0) red_s[warp] = s;
    __syncthreads();
    float S = 0.f;
    #pragma unroll
    for (int i = 0; i < 8; i++) S += red_s[i];

    float f = 0.125f / S * 1.44269504089f;   // fold 1/sqrt(E) and log2(e)
    ((uint2*)g_wh)[row * (L_SZ / 4) + tid] =
        pack4h(make_float4(e0 * f, e1 * f, e2 * f, e3 * f));
}

// -- kernel 2: fp16 mma flash attention, 4-slot ring, barrier per 2 tiles ----
// Schedule: top of pair-iter st: wait pair(st) landed + barrier (all warps done
// reading pair(st-2) -> its slots (st+2)&3 are free) -> issue pair(st+2) there.
__global__ void __launch_bounds__(THREADS, 2)
flash_kernel(const float* __restrict__ q, float* __restrict__ out) {
    extern __shared__ char smem[];
    const uint32_t sb = smem_u32(smem);

    const int tid = threadIdx.x;
    const int warp = tid >> 5, lane = tid & 31;    // 8 M-warps, 16 rows each
    const int g = lane >> 2, t4 = lane & 3;
    const int l0 = blockIdx.x * BM;
    const int bh = blockIdx.y;

    const size_t base = (size_t)(bh >> 3) * (L_SZ * RS) + (size_t)(bh & 7) * E_SZ;
    const float* qb = q + base;
    float* ob = out + base;
    const __half* khb = g_kh + (size_t)bh * (L_SZ * E_SZ);
    const __half* vhb = g_vh + (size_t)bh * (L_SZ * E_SZ);
    const __half* whb = g_wh + (size_t)(l0 + 16 * warp + g) * L_SZ + 2 * t4;

    // chunk assignment for cp.async tile fills: 2 x 16B per thread per tile
    const int c0r = tid >> 3, c0c = (tid & 7) << 4;      // rows 0..31 / +32

    // ---- prologue: issue pair (0,1) only; stage Q ----
    #pragma unroll
    for (int u = 0; u < 2; u++) {
        const int s0 = u * BN;
        CPA16(sb + KO(u) + swz(c0r, c0c), khb + (s0 + c0r) * 64 + (c0c >> 1));
        CPA16(sb + KO(u) + swz(c0r + 32, c0c), khb + (s0 + c0r + 32) * 64 + (c0c >> 1));
        CPA16(sb + VO(u) + swz(c0r, c0c), vhb + (s0 + c0r) * 64 + (c0c >> 1));
        CPA16(sb + VO(u) + swz(c0r + 32, c0c), vhb + (s0 + c0r + 32) * 64 + (c0c >> 1));
    }
    CPA_COMMIT();
    #pragma unroll
    for (int i = 0; i < 8; i++) {
        int e4 = i * THREADS + tid;              // 2048 float4
        int r = e4 >> 4, c = (e4 & 15) << 2;
        float4 x = *(const float4*)(qb + (size_t)(l0 + r) * RS + c);
        *(uint2*)(smem + QO + swz(r, c * 2)) = pack4h(x);
    }
    CPA_WAIT0();        // pair (0,1) landed
    __syncthreads();    // Q + pair(0,1) visible to all warps

    // ---- persistent Q fragments (rows 16*warp..+15, k=0..63): 16 regs ----
    uint32_t QA[4][4];
    #pragma unroll
    for (int kbk = 0; kbk < 4; kbk++)
        LDSM4(QA[kbk][0], QA[kbk][1], QA[kbk][2], QA[kbk][3],
              sb + QO + swz(16 * warp + (lane & 15), kbk * 32 + ((lane >> 4) << 4)));

    float O[8][4];
    #pragma unroll
    for (int nb = 0; nb < 8; nb++) {
        O[nb][0] = 0.f; O[nb][1] = 0.f; O[nb][2] = 0.f; O[nb][3] = 0.f;
    }
    float ls0 = 0.f, ls1 = 0.f;

    for (int st = 0; st < NT; st += 2) {
        // pair barrier (st=0 handled in prologue): pair(st) resident, slots of
        // pair(st-2) == slots of pair(st+2) are free after this barrier
        if (st) {
            CPA_WAIT0();
            __syncthreads();
        }

        // issue pair (st+2, st+3) into the two slots freed by the barrier
        if (st + 2 < NT) {
            #pragma unroll
            for (int u = 0; u < 2; u++) {
                const int t = st + 2 + u;
                const int sl = t & 3;
                const int s0 = t * BN;
                CPA16(sb + KO(sl) + swz(c0r, c0c), khb + (s0 + c0r) * 64 + (c0c >> 1));
                CPA16(sb + KO(sl) + swz(c0r + 32, c0c), khb + (s0 + c0r + 32) * 64 + (c0c >> 1));
                CPA16(sb + VO(sl) + swz(c0r, c0c), vhb + (s0 + c0r) * 64 + (c0c >> 1));
                CPA16(sb + VO(sl) + swz(c0r + 32, c0c), vhb + (s0 + c0r + 32) * 64 + (c0c >> 1));
            }
            CPA_COMMIT();
        }

        // ---- process the two resident tiles (warps may skew freely) ----
        #pragma unroll
        for (int u = 0; u < 2; u++) {
            const int t = st + u;
            const int sl = t & 3;

            // prefetch w fragments (fp16 half2, L2-resident) — hidden by S MMAs
            uint32_t wl0[8], wl1[8];
            {
                const __half* wr = whb + t * BN;
                #pragma unroll
                for (int nb = 0; nb < 8; nb++) {
                    wl0[nb] = *(const uint32_t*)(wr + nb * 8);
                    wl1[nb] = *(const uint32_t*)(wr + nb * 8 + 8 * L_SZ);
                }
            }

            // ---- S = Q K^T : 16 LDSM4 + 32 MMA (16 rows x 64 s-cols) ----
            float S[8][4];
            #pragma unroll
            for (int nb = 0; nb < 8; nb++) {
                S[nb][0] = 0.f; S[nb][1] = 0.f; S[nb][2] = 0.f; S[nb][3] = 0.f;
            }
            #pragma unroll
            for (int s16 = 0; s16 < 4; s16++) {
                #pragma unroll
                for (int kbk = 0; kbk < 4; kbk++) {
                    uint32_t Kf0, Kf1, Kf2, Kf3;
                    int rk = s16 * 16 + (lane & 7) + ((lane & 16) >> 1);
                    int cbk = kbk * 32 + (((lane >> 3) & 1) << 4);
                    LDSM4(Kf0, Kf1, Kf2, Kf3, sb + KO(sl) + swz(rk, cbk));
                    MMA16816(S[2 * s16],     QA[kbk][0], QA[kbk][1], QA[kbk][2], QA[kbk][3], Kf0, Kf1);
                    MMA16816(S[2 * s16 + 1], QA[kbk][0], QA[kbk][1], QA[kbk][2], QA[kbk][3], Kf2, Kf3);
                }
            }

            // ---- softmax fp32: p = exp2(s*w') (w' has log2e; no max) ----
            uint32_t P[4][4];
            #pragma unroll
            for (int nb = 0; nb < 8; nb++) {
                float2 wa = __half22float2(*(half2*)&wl0[nb]);
                float2 wb = __half22float2(*(half2*)&wl1[nb]);
                float e0 = ex2f(S[nb][0] * wa.x);
                float e1 = ex2f(S[nb][1] * wa.y);
                float e2 = ex2f(S[nb][2] * wb.x);
                float e3 = ex2f(S[nb][3] * wb.y);
                ls0 += e0 + e1;
                ls1 += e2 + e3;
                P[nb >> 1][(nb & 1) * 2]     = pack2h(e0, e1);
                P[nb >> 1][(nb & 1) * 2 + 1] = pack2h(e2, e3);
            }

            // ---- O += P V : 16 LDSM4T + 32 MMA (full k=64) ----
            #pragma unroll
            for (int kb = 0; kb < 4; kb++) {
                uint32_t Vf[4][4];
                #pragma unroll
                for (int n16 = 0; n16 < 4; n16++) {
                    int rv = kb * 16 + (lane & 15);
                    int cbv = n16 * 32 + ((lane >> 4) << 4);
                    LDSM4T(Vf[n16][0], Vf[n16][1], Vf[n16][2], Vf[n16][3],
                           sb + VO(sl) + swz(rv, cbv));
                }
                #pragma unroll
                for (int nb = 0; nb < 8; nb++)
                    MMA16816(O[nb], P[kb][0], P[kb][1], P[kb][2], P[kb][3],
                             Vf[nb >> 1][(nb & 1) * 2], Vf[nb >> 1][(nb & 1) * 2 + 1]);
            }
        }
    }

    // ---- epilogue: quad-reduce ls, scale, store directly ----
    ls0 += __shfl_xor_sync(0xffffffffu, ls0, 1);
    ls0 += __shfl_xor_sync(0xffffffffu, ls0, 2);
    ls1 += __shfl_xor_sync(0xffffffffu, ls1, 1);
    ls1 += __shfl_xor_sync(0xffffffffu, ls1, 2);
    float inv0 = 1.f / ls0;
    float inv1 = 1.f / ls1;

    int r = l0 + 16 * warp + g;
    #pragma unroll
    for (int nb = 0; nb < 8; nb++) {
        int c = 8 * nb + 2 * t4;
        *(float2*)(ob + (size_t)r * RS + c) =
            make_float2(O[nb][0] * inv0, O[nb][1] * inv0);
        *(float2*)(ob + (size_t)(r + 8) * RS + c) =
            make_float2(O[nb][2] * inv1, O[nb][3] * inv1);
    }
}

// ---------------- launcher ----------------
extern "C" void kernel_launch(void* const* d_in, const int* in_sizes, int n_in,
                              void* d_out, int out_size) {
    const float* q   = (const float*)d_in[0];
    const float* k   = (const float*)d_in[1];
    const float* v   = (const float*)d_in[2];
    const float* wm  = (const float*)d_in[3];
    const float* tau = (const float*)d_in[4];
    // d_in[5] = attn_mask, unused (mask_flag=False)

    cudaFuncSetAttribute(flash_kernel, cudaFuncAttributeMaxDynamicSharedMemorySize, SMEM_BYTES);

    prep_kernel<<<8192 + 1024, 256>>>(k, v, wm, tau);

    dim3 grid(L_SZ / BM, B_SZ * H_SZ);
    flash_kernel<<<grid, THREADS, SMEM_BYTES>>>(q, (float*)d_out);
}

// round 15
// speedup vs baseline: 1.0429x; 1.0429x over previous
#include <cuda_runtime.h>
#include <cuda_fp16.h>
#include <cstdint>
#include <math.h>

// ---------------- problem constants ----------------
#define B_SZ 16
#define H_SZ 8
#define L_SZ 1024
#define E_SZ 64
#define RS   512                 // floats between consecutive rows (H*E)

#define BM 128
#define BN 64
#define NT 16
#define THREADS 256

// ---------------- smem byte map (fp16 tiles, 128B swizzled rows) ------------
#define QO   0                       // 128 x 64 fp16 = 16 KB
#define KO(b) (16384 + (b) * 8192)   // 64 x 64 fp16, 3-stage ring
#define VO(b) (40960 + (b) * 8192)
#define SMEM_BYTES 65536

// precomputed tensors
__device__ __half g_kh[B_SZ * H_SZ * L_SZ * E_SZ];   // [bh][s][e] fp16
__device__ __half g_vh[B_SZ * H_SZ * L_SZ * E_SZ];
// fragment-packed modulation weights (half2 entries):
// g_wp[(row*4 + t4)*128 + tile*8 + nb] = half2(w[row][c], w[row][c+1]),
//   c = 2*t4 + 8*(tile*8+nb);  w = softmax(wm/softplus(tau)) * (1/8) * log2(e)
__device__ uint32_t g_wp[L_SZ * 512];

// ---------------- helpers ----------------
__device__ __forceinline__ uint32_t smem_u32(const void* p) {
    uint32_t a;
    asm("{ .reg .u64 t; cvta.to.shared.u64 t, %1; cvt.u32.u64 %0, t; }" : "=r"(a) : "l"(p));
    return a;
}
// 128B-row XOR swizzle
__device__ __forceinline__ uint32_t swz(int r, int cb) {
    return (uint32_t)(r * 128 + (cb ^ ((r & 7) << 4)));
}
__device__ __forceinline__ float ex2f(float x) {
    float y; asm("ex2.approx.f32 %0, %1;" : "=f"(y) : "f"(x)); return y;
}

#define LDSM4(d0,d1,d2,d3,a) \
    asm volatile("ldmatrix.sync.aligned.m8n8.x4.shared.b16 {%0,%1,%2,%3}, [%4];" \
        : "=r"(d0),"=r"(d1),"=r"(d2),"=r"(d3) : "r"(a))
#define LDSM4T(d0,d1,d2,d3,a) \
    asm volatile("ldmatrix.sync.aligned.m8n8.x4.trans.shared.b16 {%0,%1,%2,%3}, [%4];" \
        : "=r"(d0),"=r"(d1),"=r"(d2),"=r"(d3) : "r"(a))
#define MMA16816(c, a0,a1,a2,a3, b0,b1) \
    asm volatile("mma.sync.aligned.m16n8k16.row.col.f32.f16.f16.f32 " \
        "{%0,%1,%2,%3},{%4,%5,%6,%7},{%8,%9},{%0,%1,%2,%3};" \
        : "+f"((c)[0]),"+f"((c)[1]),"+f"((c)[2]),"+f"((c)[3]) \
        : "r"(a0),"r"(a1),"r"(a2),"r"(a3),"r"(b0),"r"(b1))
#define CPA16(dst, src) \
    asm volatile("cp.async.cg.shared.global [%0], [%1], 16;" :: "r"(dst), "l"(src))
#define CPA_COMMIT() asm volatile("cp.async.commit_group;" ::: "memory")
#define CPA_WAIT0()  asm volatile("cp.async.wait_group 0;" ::: "memory")
#define CPA_WAIT1()  asm volatile("cp.async.wait_group 1;" ::: "memory")

__device__ __forceinline__ uint2 pack4h(float4 x) {
    half2 h0 = __floats2half2_rn(x.x, x.y);
    half2 h1 = __floats2half2_rn(x.z, x.w);
    return make_uint2(*(uint32_t*)&h0, *(uint32_t*)&h1);
}
__device__ __forceinline__ uint32_t pack2h(float a, float b) {
    half2 h = __floats2half2_rn(a, b);
    return *(uint32_t*)&h;
}

// ------- kernel 0: fused prep (K/V fp32->fp16 bh-major; packed w) ----------
__global__ void prep_kernel(const float* __restrict__ k, const float* __restrict__ v,
                            const float* __restrict__ wm, const float* __restrict__ tau) {
    if (blockIdx.x < 8192) {
        // K/V convert: one half4 per thread per tensor
        int o = blockIdx.x * 256 + threadIdx.x;      // half4 index, 2^21 total
        int e4 = o & 15;
        int s  = (o >> 4) & 1023;
        int bh = o >> 14;
        int b = bh >> 3, h = bh & 7;
        size_t in = (((size_t)b * L_SZ + s) * H_SZ + h) * 16 + e4;   // float4 units
        ((uint2*)g_kh)[o] = pack4h(((const float4*)k)[in]);
        ((uint2*)g_vh)[o] = pack4h(((const float4*)v)[in]);
        return;
    }
    // w modulation row -> fragment-packed fp16 layout
    __shared__ float red_m[8];
    __shared__ float red_s[8];
    const int row = blockIdx.x - 8192, tid = threadIdx.x;
    const int warp = tid >> 5, lane = tid & 31;

    float t = tau[row];
    float sp = (t > 20.f) ? t : log1pf(__expf(t));
    float inv = 1.f / sp;

    float4 x = reinterpret_cast<const float4*>(wm + (size_t)row * L_SZ)[tid];
    x.x *= inv; x.y *= inv; x.z *= inv; x.w *= inv;

    float mx = fmaxf(fmaxf(x.x, x.y), fmaxf(x.z, x.w));
    #pragma unroll
    for (int o = 16; o; o >>= 1) mx = fmaxf(mx, __shfl_xor_sync(0xffffffffu, mx, o));
    if (lane == 0) red_m[warp] = mx;
    __syncthreads();
    float M = red_m[0];
    #pragma unroll
    for (int i = 1; i < 8; i++) M = fmaxf(M, red_m[i]);

    float e0 = __expf(x.x - M), e1 = __expf(x.y - M);
    float e2 = __expf(x.z - M), e3 = __expf(x.w - M);
    float s = e0 + e1 + e2 + e3;
    #pragma unroll
    for (int o = 16; o; o >>= 1) s += __shfl_xor_sync(0xffffffffu, s, o);
    if (lane == 0) red_s[warp] = s;
    __syncthreads();
    float S = 0.f;
    #pragma unroll
    for (int i = 0; i < 8; i++) S += red_s[i];

    float f = 0.125f / S * 1.44269504089f;   // fold 1/sqrt(E) and log2(e)
    // this thread owns cols 4*tid..4*tid+3 -> half2 pairs p0=2*tid, p1=2*tid+1
    // pair p -> t4 = p & 3, frag index = p >> 2
    int p0 = 2 * tid, p1 = 2 * tid + 1;
    g_wp[(row * 4 + (p0 & 3)) * 128 + (p0 >> 2)] = pack2h(e0 * f, e1 * f);
    g_wp[(row * 4 + (p1 & 3)) * 128 + (p1 >> 2)] = pack2h(e2 * f, e3 * f);
}

// -- kernel 2: fp16 mma flash attention, 3-stage ring, packed-w LDG.128 -----
__global__ void __launch_bounds__(THREADS, 2)
flash_kernel(const float* __restrict__ q, float* __restrict__ out) {
    extern __shared__ char smem[];
    const uint32_t sb = smem_u32(smem);

    const int tid = threadIdx.x;
    const int warp = tid >> 5, lane = tid & 31;    // 8 M-warps, 16 rows each
    const int g = lane >> 2, t4 = lane & 3;
    const int l0 = blockIdx.x * BM;
    const int bh = blockIdx.y;

    const size_t base = (size_t)(bh >> 3) * (L_SZ * RS) + (size_t)(bh & 7) * E_SZ;
    const float* qb = q + base;
    float* ob = out + base;
    const __half* khb = g_kh + (size_t)bh * (L_SZ * E_SZ);
    const __half* vhb = g_vh + (size_t)bh * (L_SZ * E_SZ);
    // packed w base for this thread's two rows (r and r+8)
    const uint32_t* wp0 = g_wp + ((size_t)(l0 + 16 * warp + g) * 4 + t4) * 128;
    const uint32_t* wp1 = wp0 + 8 * 4 * 128;

    // chunk assignment for cp.async tile fills: 2 x 16B per thread per tile
    const int c0r = tid >> 3, c0c = (tid & 7) << 4;      // rows 0..31 / +32

    // ---- prologue: issue tiles 0 and 1, stage Q ----
    #pragma unroll
    for (int t = 0; t < 2; t++) {
        const int s0 = t * BN;
        CPA16(sb + KO(t) + swz(c0r, c0c), khb + (s0 + c0r) * 64 + (c0c >> 1));
        CPA16(sb + KO(t) + swz(c0r + 32, c0c), khb + (s0 + c0r + 32) * 64 + (c0c >> 1));
        CPA16(sb + VO(t) + swz(c0r, c0c), vhb + (s0 + c0r) * 64 + (c0c >> 1));
        CPA16(sb + VO(t) + swz(c0r + 32, c0c), vhb + (s0 + c0r + 32) * 64 + (c0c >> 1));
        CPA_COMMIT();
    }
    #pragma unroll
    for (int i = 0; i < 8; i++) {
        int e4 = i * THREADS + tid;              // 2048 float4
        int r = e4 >> 4, c = (e4 & 15) << 2;
        float4 x = *(const float4*)(qb + (size_t)(l0 + r) * RS + c);
        *(uint2*)(smem + QO + swz(r, c * 2)) = pack4h(x);
    }
    CPA_WAIT1();        // tile 0 landed
    __syncthreads();    // Q + tile 0 visible to all warps

    // ---- persistent Q fragments (rows 16*warp..+15, k=0..63): 16 regs ----
    uint32_t QA[4][4];
    #pragma unroll
    for (int kbk = 0; kbk < 4; kbk++)
        LDSM4(QA[kbk][0], QA[kbk][1], QA[kbk][2], QA[kbk][3],
              sb + QO + swz(16 * warp + (lane & 15), kbk * 32 + ((lane >> 4) << 4)));

    float O[8][4];
    #pragma unroll
    for (int nb = 0; nb < 8; nb++) {
        O[nb][0] = 0.f; O[nb][1] = 0.f; O[nb][2] = 0.f; O[nb][3] = 0.f;
    }
    float ls0 = 0.f, ls1 = 0.f;

    for (int st = 0; st < NT; st++) {
        const int buf = st % 3;

        // issue cp.async for tile st+2 into its ring slot (read at st-1, freed)
        if (st + 2 < NT) {
            const int nb3 = (st + 2) % 3;
            const int s0n = (st + 2) * BN;
            CPA16(sb + KO(nb3) + swz(c0r, c0c), khb + (s0n + c0r) * 64 + (c0c >> 1));
            CPA16(sb + KO(nb3) + swz(c0r + 32, c0c), khb + (s0n + c0r + 32) * 64 + (c0c >> 1));
            CPA16(sb + VO(nb3) + swz(c0r, c0c), vhb + (s0n + c0r) * 64 + (c0c >> 1));
            CPA16(sb + VO(nb3) + swz(c0r + 32, c0c), vhb + (s0n + c0r + 32) * 64 + (c0c >> 1));
            CPA_COMMIT();
        }

        // prefetch w fragments: 4 x LDG.128 (contiguous packed layout)
        uint4 wa0 = *(const uint4*)(wp0 + st * 8);
        uint4 wa1 = *(const uint4*)(wp0 + st * 8 + 4);
        uint4 wb0 = *(const uint4*)(wp1 + st * 8);
        uint4 wb1 = *(const uint4*)(wp1 + st * 8 + 4);
        uint32_t wl0[8] = {wa0.x, wa0.y, wa0.z, wa0.w, wa1.x, wa1.y, wa1.z, wa1.w};
        uint32_t wl1[8] = {wb0.x, wb0.y, wb0.z, wb0.w, wb1.x, wb1.y, wb1.z, wb1.w};

        // ---- S = Q K^T : 16 LDSM4 + 32 MMA (16 rows x 64 s-cols) ----
        float S[8][4];
        #pragma unroll
        for (int nb = 0; nb < 8; nb++) {
            S[nb][0] = 0.f; S[nb][1] = 0.f; S[nb][2] = 0.f; S[nb][3] = 0.f;
        }
        #pragma unroll
        for (int s16 = 0; s16 < 4; s16++) {
            #pragma unroll
            for (int kbk = 0; kbk < 4; kbk++) {
                uint32_t Kf0, Kf1, Kf2, Kf3;
                int rk = s16 * 16 + (lane & 7) + ((lane & 16) >> 1);
                int cbk = kbk * 32 + (((lane >> 3) & 1) << 4);
                LDSM4(Kf0, Kf1, Kf2, Kf3, sb + KO(buf) + swz(rk, cbk));
                MMA16816(S[2 * s16],     QA[kbk][0], QA[kbk][1], QA[kbk][2], QA[kbk][3], Kf0, Kf1);
                MMA16816(S[2 * s16 + 1], QA[kbk][0], QA[kbk][1], QA[kbk][2], QA[kbk][3], Kf2, Kf3);
            }
        }

        // ---- softmax fp32: p = exp2(s*w') (w' has log2e; |z|<<1 -> no max) ----
        uint32_t P[4][4];
        #pragma unroll
        for (int nb = 0; nb < 8; nb++) {
            float2 wa = __half22float2(*(half2*)&wl0[nb]);
            float2 wb = __half22float2(*(half2*)&wl1[nb]);
            float e0 = ex2f(S[nb][0] * wa.x);
            float e1 = ex2f(S[nb][1] * wa.y);
            float e2 = ex2f(S[nb][2] * wb.x);
            float e3 = ex2f(S[nb][3] * wb.y);
            ls0 += e0 + e1;
            ls1 += e2 + e3;
            P[nb >> 1][(nb & 1) * 2]     = pack2h(e0, e1);
            P[nb >> 1][(nb & 1) * 2 + 1] = pack2h(e2, e3);
        }

        // ---- O += P V : 16 LDSM4T + 32 MMA (full k=64) ----
        #pragma unroll
        for (int kb = 0; kb < 4; kb++) {
            uint32_t Vf[4][4];
            #pragma unroll
            for (int n16 = 0; n16 < 4; n16++) {
                int rv = kb * 16 + (lane & 15);
                int cbv = n16 * 32 + ((lane >> 4) << 4);
                LDSM4T(Vf[n16][0], Vf[n16][1], Vf[n16][2], Vf[n16][3],
                       sb + VO(buf) + swz(rv, cbv));
            }
            #pragma unroll
            for (int nb = 0; nb < 8; nb++)
                MMA16816(O[nb], P[kb][0], P[kb][1], P[kb][2], P[kb][3],
                         Vf[nb >> 1][(nb & 1) * 2], Vf[nb >> 1][(nb & 1) * 2 + 1]);
        }

        // ensure tile st+1 landed; barrier frees this iter's ring slot
        if (st < NT - 1) {
            if (st + 2 < NT) CPA_WAIT1(); else CPA_WAIT0();
            __syncthreads();
        }
    }

    // ---- epilogue: quad-reduce ls, scale, store directly ----
    ls0 += __shfl_xor_sync(0xffffffffu, ls0, 1);
    ls0 += __shfl_xor_sync(0xffffffffu, ls0, 2);
    ls1 += __shfl_xor_sync(0xffffffffu, ls1, 1);
    ls1 += __shfl_xor_sync(0xffffffffu, ls1, 2);
    float inv0 = 1.f / ls0;
    float inv1 = 1.f / ls1;

    int r = l0 + 16 * warp + g;
    #pragma unroll
    for (int nb = 0; nb < 8; nb++) {
        int c = 8 * nb + 2 * t4;
        *(float2*)(ob + (size_t)r * RS + c) =
            make_float2(O[nb][0] * inv0, O[nb][1] * inv0);
        *(float2*)(ob + (size_t)(r + 8) * RS + c) =
            make_float2(O[nb][2] * inv1, O[nb][3] * inv1);
    }
}

// ---------------- launcher ----------------
extern "C" void kernel_launch(void* const* d_in, const int* in_sizes, int n_in,
                              void* d_out, int out_size) {
    const float* q   = (const float*)d_in[0];
    const float* k   = (const float*)d_in[1];
    const float* v   = (const float*)d_in[2];
    const float* wm  = (const float*)d_in[3];
    const float* tau = (const float*)d_in[4];
    // d_in[5] = attn_mask, unused (mask_flag=False)

    cudaFuncSetAttribute(flash_kernel, cudaFuncAttributeMaxDynamicSharedMemorySize, SMEM_BYTES);

    prep_kernel<<<8192 + 1024, 256>>>(k, v, wm, tau);

    dim3 grid(L_SZ / BM, B_SZ * H_SZ);
    flash_kernel<<<grid, THREADS, SMEM_BYTES>>>(q, (float*)d_out);
}

// round 16
// speedup vs baseline: 1.0964x; 1.0514x over previous
#include <cuda_runtime.h>
#include <cuda_fp16.h>
#include <cstdint>
#include <math.h>

// ---------------- problem constants ----------------
#define B_SZ 16
#define H_SZ 8
#define L_SZ 1024
#define E_SZ 64
#define RS   512                 // floats between consecutive rows (H*E)

#define BM 128
#define BN 64
#define NT 16
#define THREADS 128

// ---------------- smem byte map (fp16 tiles, 128B swizzled rows) ------------
#define QO   0                       // 128 x 64 fp16 = 16 KB
#define KO(b) (16384 + (b) * 8192)   // 64 x 64 fp16, 3-stage ring
#define VO(b) (40960 + (b) * 8192)
#define SMEM_BYTES 65536

// precomputed tensors
__device__ __half g_kh[B_SZ * H_SZ * L_SZ * E_SZ];   // [bh][s][e] fp16
__device__ __half g_vh[B_SZ * H_SZ * L_SZ * E_SZ];
// fragment-packed modulation weights (half2 entries):
// g_wp[(row*4 + t4)*128 + tile*8 + nb] = half2(w[row][c], w[row][c+1]),
//   c = 2*t4 + 8*(tile*8+nb);  w = softmax(wm/softplus(tau)) * (1/8) * log2(e)
__device__ uint32_t g_wp[L_SZ * 512];

// ---------------- helpers ----------------
__device__ __forceinline__ uint32_t smem_u32(const void* p) {
    uint32_t a;
    asm("{ .reg .u64 t; cvta.to.shared.u64 t, %1; cvt.u32.u64 %0, t; }" : "=r"(a) : "l"(p));
    return a;
}
// 128B-row XOR swizzle
__device__ __forceinline__ uint32_t swz(int r, int cb) {
    return (uint32_t)(r * 128 + (cb ^ ((r & 7) << 4)));
}

#define LDSM4(d0,d1,d2,d3,a) \
    asm volatile("ldmatrix.sync.aligned.m8n8.x4.shared.b16 {%0,%1,%2,%3}, [%4];" \
        : "=r"(d0),"=r"(d1),"=r"(d2),"=r"(d3) : "r"(a))
#define LDSM4T(d0,d1,d2,d3,a) \
    asm volatile("ldmatrix.sync.aligned.m8n8.x4.trans.shared.b16 {%0,%1,%2,%3}, [%4];" \
        : "=r"(d0),"=r"(d1),"=r"(d2),"=r"(d3) : "r"(a))
// fp32-accum MMA (PV path)
#define MMA16816(c, a0,a1,a2,a3, b0,b1) \
    asm volatile("mma.sync.aligned.m16n8k16.row.col.f32.f16.f16.f32 " \
        "{%0,%1,%2,%3},{%4,%5,%6,%7},{%8,%9},{%0,%1,%2,%3};" \
        : "+f"((c)[0]),"+f"((c)[1]),"+f"((c)[2]),"+f"((c)[3]) \
        : "r"(a0),"r"(a1),"r"(a2),"r"(a3),"r"(b0),"r"(b1))
// fp16-accum MMA (S path; D/C are 2 x half2 regs)
#define MMA16816H(c, a0,a1,a2,a3, b0,b1) \
    asm volatile("mma.sync.aligned.m16n8k16.row.col.f16.f16.f16.f16 " \
        "{%0,%1},{%2,%3,%4,%5},{%6,%7},{%0,%1};" \
        : "+r"((c)[0]),"+r"((c)[1]) \
        : "r"(a0),"r"(a1),"r"(a2),"r"(a3),"r"(b0),"r"(b1))
#define CPA16(dst, src) \
    asm volatile("cp.async.cg.shared.global [%0], [%1], 16;" :: "r"(dst), "l"(src))
#define CPA_COMMIT() asm volatile("cp.async.commit_group;" ::: "memory")
#define CPA_WAIT0()  asm volatile("cp.async.wait_group 0;" ::: "memory")
#define CPA_WAIT1()  asm volatile("cp.async.wait_group 1;" ::: "memory")
#define HMUL2(out, a, b) \
    asm("mul.rn.f16x2 %0, %1, %2;" : "=r"(out) : "r"(a), "r"(b))
#define EX2H2(out, a) \
    asm("ex2.approx.f16x2 %0, %1;" : "=r"(out) : "r"(a))

__device__ __forceinline__ uint2 pack4h(float4 x) {
    half2 h0 = __floats2half2_rn(x.x, x.y);
    half2 h1 = __floats2half2_rn(x.z, x.w);
    return make_uint2(*(uint32_t*)&h0, *(uint32_t*)&h1);
}
__device__ __forceinline__ uint32_t pack2h(float a, float b) {
    half2 h = __floats2half2_rn(a, b);
    return *(uint32_t*)&h;
}

// ------- kernel 0: fused prep (K/V fp32->fp16 bh-major; packed w) ----------
__global__ void prep_kernel(const float* __restrict__ k, const float* __restrict__ v,
                            const float* __restrict__ wm, const float* __restrict__ tau) {
    if (blockIdx.x < 8192) {
        int o = blockIdx.x * 256 + threadIdx.x;      // half4 index, 2^21 total
        int e4 = o & 15;
        int s  = (o >> 4) & 1023;
        int bh = o >> 14;
        int b = bh >> 3, h = bh & 7;
        size_t in = (((size_t)b * L_SZ + s) * H_SZ + h) * 16 + e4;   // float4 units
        ((uint2*)g_kh)[o] = pack4h(((const float4*)k)[in]);
        ((uint2*)g_vh)[o] = pack4h(((const float4*)v)[in]);
        return;
    }
    // w modulation row -> fragment-packed fp16 layout
    __shared__ float red_m[8];
    __shared__ float red_s[8];
    const int row = blockIdx.x - 8192, tid = threadIdx.x;
    const int warp = tid >> 5, lane = tid & 31;

    float t = tau[row];
    float sp = (t > 20.f) ? t : log1pf(__expf(t));
    float inv = 1.f / sp;

    float4 x = reinterpret_cast<const float4*>(wm + (size_t)row * L_SZ)[tid];
    x.x *= inv; x.y *= inv; x.z *= inv; x.w *= inv;

    float mx = fmaxf(fmaxf(x.x, x.y), fmaxf(x.z, x.w));
    #pragma unroll
    for (int o = 16; o; o >>= 1) mx = fmaxf(mx, __shfl_xor_sync(0xffffffffu, mx, o));
    if (lane == 0) red_m[warp] = mx;
    __syncthreads();
    float M = red_m[0];
    #pragma unroll
    for (int i = 1; i < 8; i++) M = fmaxf(M, red_m[i]);

    float e0 = __expf(x.x - M), e1 = __expf(x.y - M);
    float e2 = __expf(x.z - M), e3 = __expf(x.w - M);
    float s = e0 + e1 + e2 + e3;
    #pragma unroll
    for (int o = 16; o; o >>= 1) s += __shfl_xor_sync(0xffffffffu, s, o);
    if (lane == 0) red_s[warp] = s;
    __syncthreads();
    float S = 0.f;
    #pragma unroll
    for (int i = 0; i < 8; i++) S += red_s[i];

    float f = 0.125f / S * 1.44269504089f;   // fold 1/sqrt(E) and log2(e)
    int p0 = 2 * tid, p1 = 2 * tid + 1;
    g_wp[(row * 4 + (p0 & 3)) * 128 + (p0 >> 2)] = pack2h(e0 * f, e1 * f);
    g_wp[(row * 4 + (p1 & 3)) * 128 + (p1 >> 2)] = pack2h(e2 * f, e3 * f);
}

// -- kernel 2: fat-warp flash attention: 4 warps x 32 rows, fp16-S, 2 CTA/SM -
__global__ void __launch_bounds__(THREADS, 2)
flash_kernel(const float* __restrict__ q, float* __restrict__ out) {
    extern __shared__ char smem[];
    const uint32_t sb = smem_u32(smem);

    const int tid = threadIdx.x;
    const int warp = tid >> 5, lane = tid & 31;    // 4 M-warps, 32 rows each
    const int g = lane >> 2, t4 = lane & 3;
    const int l0 = blockIdx.x * BM;
    const int bh = blockIdx.y;

    const size_t base = (size_t)(bh >> 3) * (L_SZ * RS) + (size_t)(bh & 7) * E_SZ;
    const float* qb = q + base;
    float* ob = out + base;
    const __half* khb = g_kh + (size_t)bh * (L_SZ * E_SZ);
    const __half* vhb = g_vh + (size_t)bh * (L_SZ * E_SZ);
    // packed-w streams for this thread's 4 rows: 32w+16mb+8h+g
    const uint32_t* wpp[2][2];
    wpp[0][0] = g_wp + ((size_t)(l0 + 32 * warp + g) * 4 + t4) * 128;
    wpp[0][1] = wpp[0][0] + 8 * 4 * 128;
    wpp[1][0] = wpp[0][0] + 16 * 4 * 128;
    wpp[1][1] = wpp[0][0] + 24 * 4 * 128;

    // cp.async chunk assignment: 4 x 16B per thread per tensor per tile
    const int c0r = tid >> 3, c0c = (tid & 7) << 4;      // rows c0r + 16j

    // ---- prologue: issue tiles 0 and 1, stage Q ----
    #pragma unroll
    for (int t = 0; t < 2; t++) {
        const int s0 = t * BN;
        #pragma unroll
        for (int j = 0; j < 4; j++) {
            int r = c0r + 16 * j;
            CPA16(sb + KO(t) + swz(r, c0c), khb + (s0 + r) * 64 + (c0c >> 1));
            CPA16(sb + VO(t) + swz(r, c0c), vhb + (s0 + r) * 64 + (c0c >> 1));
        }
        CPA_COMMIT();
    }
    #pragma unroll
    for (int i = 0; i < 16; i++) {
        int e4 = i * THREADS + tid;              // 2048 float4
        int r = e4 >> 4, c = (e4 & 15) << 2;
        float4 x = *(const float4*)(qb + (size_t)(l0 + r) * RS + c);
        *(uint2*)(smem + QO + swz(r, c * 2)) = pack4h(x);
    }
    CPA_WAIT1();        // tile 0 landed
    __syncthreads();    // Q + tile 0 visible to all warps

    // ---- persistent Q fragments (rows 32w..+31, k=0..63): 32 regs ----
    uint32_t QA[2][4][4];
    #pragma unroll
    for (int mb = 0; mb < 2; mb++)
        #pragma unroll
        for (int kbk = 0; kbk < 4; kbk++)
            LDSM4(QA[mb][kbk][0], QA[mb][kbk][1], QA[mb][kbk][2], QA[mb][kbk][3],
                  sb + QO + swz(32 * warp + 16 * mb + (lane & 15),
                                kbk * 32 + ((lane >> 4) << 4)));

    float O[2][8][4];
    #pragma unroll
    for (int mb = 0; mb < 2; mb++)
        #pragma unroll
        for (int nb = 0; nb < 8; nb++) {
            O[mb][nb][0] = 0.f; O[mb][nb][1] = 0.f; O[mb][nb][2] = 0.f; O[mb][nb][3] = 0.f;
        }
    float ls[2][2] = {{0.f, 0.f}, {0.f, 0.f}};

    for (int st = 0; st < NT; st++) {
        const int buf = st % 3;

        // issue cp.async for tile st+2 into its ring slot (read at st-1, freed)
        if (st + 2 < NT) {
            const int nb3 = (st + 2) % 3;
            const int s0n = (st + 2) * BN;
            #pragma unroll
            for (int j = 0; j < 4; j++) {
                int r = c0r + 16 * j;
                CPA16(sb + KO(nb3) + swz(r, c0c), khb + (s0n + r) * 64 + (c0c >> 1));
                CPA16(sb + VO(nb3) + swz(r, c0c), vhb + (s0n + r) * 64 + (c0c >> 1));
            }
            CPA_COMMIT();
        }

        // prefetch w fragments: 8 x LDG.128 (packed layout), 32 half2 regs
        uint32_t wl[2][2][8];
        #pragma unroll
        for (int mb = 0; mb < 2; mb++)
            #pragma unroll
            for (int h = 0; h < 2; h++) {
                uint4 a = *(const uint4*)(wpp[mb][h] + st * 8);
                uint4 b = *(const uint4*)(wpp[mb][h] + st * 8 + 4);
                wl[mb][h][0] = a.x; wl[mb][h][1] = a.y; wl[mb][h][2] = a.z; wl[mb][h][3] = a.w;
                wl[mb][h][4] = b.x; wl[mb][h][5] = b.y; wl[mb][h][6] = b.z; wl[mb][h][7] = b.w;
            }

        // ---- S = Q K^T (fp16 accum): 16 LDSM4, 64 MMA (32 rows x 64 cols) --
        uint32_t S[2][8][2];
        #pragma unroll
        for (int mb = 0; mb < 2; mb++)
            #pragma unroll
            for (int nb = 0; nb < 8; nb++) { S[mb][nb][0] = 0u; S[mb][nb][1] = 0u; }
        #pragma unroll
        for (int s16 = 0; s16 < 4; s16++) {
            #pragma unroll
            for (int kbk = 0; kbk < 4; kbk++) {
                uint32_t Kf0, Kf1, Kf2, Kf3;
                int rk = s16 * 16 + (lane & 7) + ((lane & 16) >> 1);
                int cbk = kbk * 32 + (((lane >> 3) & 1) << 4);
                LDSM4(Kf0, Kf1, Kf2, Kf3, sb + KO(buf) + swz(rk, cbk));
                #pragma unroll
                for (int mb = 0; mb < 2; mb++) {
                    MMA16816H(S[mb][2 * s16],     QA[mb][kbk][0], QA[mb][kbk][1],
                              QA[mb][kbk][2], QA[mb][kbk][3], Kf0, Kf1);
                    MMA16816H(S[mb][2 * s16 + 1], QA[mb][kbk][0], QA[mb][kbk][1],
                              QA[mb][kbk][2], QA[mb][kbk][3], Kf2, Kf3);
                }
            }
        }

        // ---- softmax fp16x2: p = ex2(S_h2 * w_h2); |z|<<1 -> no max ----
        uint32_t P[2][4][4];
        #pragma unroll
        for (int mb = 0; mb < 2; mb++)
            #pragma unroll
            for (int nb = 0; nb < 8; nb++) {
                uint32_t z0, z1, p0, p1;
                HMUL2(z0, S[mb][nb][0], wl[mb][0][nb]);   // row g
                HMUL2(z1, S[mb][nb][1], wl[mb][1][nb]);   // row g+8
                EX2H2(p0, z0);
                EX2H2(p1, z1);
                P[mb][nb >> 1][(nb & 1) * 2]     = p0;
                P[mb][nb >> 1][(nb & 1) * 2 + 1] = p1;
                float2 f0 = __half22float2(*(half2*)&p0);
                float2 f1 = __half22float2(*(half2*)&p1);
                ls[mb][0] += f0.x + f0.y;
                ls[mb][1] += f1.x + f1.y;
            }

        // ---- O += P V (fp32 accum): 16 LDSM4T, 64 MMA ----
        #pragma unroll
        for (int kb = 0; kb < 4; kb++) {
            uint32_t Vf[4][4];
            #pragma unroll
            for (int n16 = 0; n16 < 4; n16++) {
                int rv = kb * 16 + (lane & 15);
                int cbv = n16 * 32 + ((lane >> 4) << 4);
                LDSM4T(Vf[n16][0], Vf[n16][1], Vf[n16][2], Vf[n16][3],
                       sb + VO(buf) + swz(rv, cbv));
            }
            #pragma unroll
            for (int mb = 0; mb < 2; mb++)
                #pragma unroll
                for (int nb = 0; nb < 8; nb++)
                    MMA16816(O[mb][nb], P[mb][kb][0], P[mb][kb][1], P[mb][kb][2], P[mb][kb][3],
                             Vf[nb >> 1][(nb & 1) * 2], Vf[nb >> 1][(nb & 1) * 2 + 1]);
        }

        // ensure tile st+1 landed; barrier frees this iter's ring slot
        if (st < NT - 1) {
            if (st + 2 < NT) CPA_WAIT1(); else CPA_WAIT0();
            __syncthreads();
        }
    }

    // ---- epilogue: quad-reduce ls, scale, store directly ----
    #pragma unroll
    for (int mb = 0; mb < 2; mb++)
        #pragma unroll
        for (int h = 0; h < 2; h++) {
            ls[mb][h] += __shfl_xor_sync(0xffffffffu, ls[mb][h], 1);
            ls[mb][h] += __shfl_xor_sync(0xffffffffu, ls[mb][h], 2);
        }

    #pragma unroll
    for (int mb = 0; mb < 2; mb++) {
        float inv0 = 1.f / ls[mb][0];
        float inv1 = 1.f / ls[mb][1];
        int r = l0 + 32 * warp + 16 * mb + g;
        #pragma unroll
        for (int nb = 0; nb < 8; nb++) {
            int c = 8 * nb + 2 * t4;
            *(float2*)(ob + (size_t)r * RS + c) =
                make_float2(O[mb][nb][0] * inv0, O[mb][nb][1] * inv0);
            *(float2*)(ob + (size_t)(r + 8) * RS + c) =
                make_float2(O[mb][nb][2] * inv1, O[mb][nb][3] * inv1);
        }
    }
}

// ---------------- launcher ----------------
extern "C" void kernel_launch(void* const* d_in, const int* in_sizes, int n_in,
                              void* d_out, int out_size) {
    const float* q   = (const float*)d_in[0];
    const float* k   = (const float*)d_in[1];
    const float* v   = (const float*)d_in[2];
    const float* wm  = (const float*)d_in[3];
    const float* tau = (const float*)d_in[4];
    // d_in[5] = attn_mask, unused (mask_flag=False)

    cudaFuncSetAttribute(flash_kernel, cudaFuncAttributeMaxDynamicSharedMemorySize, SMEM_BYTES);

    prep_kernel<<<8192 + 1024, 256>>>(k, v, wm, tau);

    dim3 grid(L_SZ / BM, B_SZ * H_SZ);
    flash_kernel<<<grid, THREADS, SMEM_BYTES>>>(q, (float*)d_out);
}

// round 17
// speedup vs baseline: 1.4995x; 1.3676x over previous
#include <cuda_runtime.h>
#include <cuda_fp16.h>
#include <cstdint>
#include <math.h>

// ---------------- problem constants ----------------
#define B_SZ 16
#define H_SZ 8
#define L_SZ 1024
#define E_SZ 64
#define RS   512                 // floats between consecutive rows (H*E)

#define BM 128
#define BN 64
#define NT 16
#define THREADS 128

// ---------------- smem byte map (fp16 tiles, 128B swizzled rows) ------------
#define QO   0                       // 128 x 64 fp16 = 16 KB
#define KO(b) (16384 + (b) * 8192)   // 64 x 64 fp16, 3-stage ring
#define VO(b) (40960 + (b) * 8192)
#define WO(b) (65536 + (b) * 16384)  // 16 KB packed-w tile, 3-stage ring
#define SMEM_BYTES 114688

// precomputed tensors
__device__ __half g_kh[B_SZ * H_SZ * L_SZ * E_SZ];   // [bh][s][e] fp16
__device__ __half g_vh[B_SZ * H_SZ * L_SZ * E_SZ];
// tile-major fragment-packed modulation weights (half2 entries):
// g_wt[st*32768 + nb2*8192 + (row*4 + t4)*2 + nbl] = half2(w[row][c], w[row][c+1])
//   with c = st*64 + (2*nb2+nbl)*8 + 2*t4;  w = softmax(wm/softplus(tau))*(1/8)*log2(e)
__device__ uint32_t g_wt[NT * 32768];

// ---------------- helpers ----------------
__device__ __forceinline__ uint32_t smem_u32(const void* p) {
    uint32_t a;
    asm("{ .reg .u64 t; cvta.to.shared.u64 t, %1; cvt.u32.u64 %0, t; }" : "=r"(a) : "l"(p));
    return a;
}
// 128B-row XOR swizzle
__device__ __forceinline__ uint32_t swz(int r, int cb) {
    return (uint32_t)(r * 128 + (cb ^ ((r & 7) << 4)));
}

#define LDSM4(d0,d1,d2,d3,a) \
    asm volatile("ldmatrix.sync.aligned.m8n8.x4.shared.b16 {%0,%1,%2,%3}, [%4];" \
        : "=r"(d0),"=r"(d1),"=r"(d2),"=r"(d3) : "r"(a))
#define LDSM4T(d0,d1,d2,d3,a) \
    asm volatile("ldmatrix.sync.aligned.m8n8.x4.trans.shared.b16 {%0,%1,%2,%3}, [%4];" \
        : "=r"(d0),"=r"(d1),"=r"(d2),"=r"(d3) : "r"(a))
// fp32-accum MMA (PV path)
#define MMA16816(c, a0,a1,a2,a3, b0,b1) \
    asm volatile("mma.sync.aligned.m16n8k16.row.col.f32.f16.f16.f32 " \
        "{%0,%1,%2,%3},{%4,%5,%6,%7},{%8,%9},{%0,%1,%2,%3};" \
        : "+f"((c)[0]),"+f"((c)[1]),"+f"((c)[2]),"+f"((c)[3]) \
        : "r"(a0),"r"(a1),"r"(a2),"r"(a3),"r"(b0),"r"(b1))
// fp16-accum MMA (S path; D/C are 2 x half2 regs)
#define MMA16816H(c, a0,a1,a2,a3, b0,b1) \
    asm volatile("mma.sync.aligned.m16n8k16.row.col.f16.f16.f16.f16 " \
        "{%0,%1},{%2,%3,%4,%5},{%6,%7},{%0,%1};" \
        : "+r"((c)[0]),"+r"((c)[1]) \
        : "r"(a0),"r"(a1),"r"(a2),"r"(a3),"r"(b0),"r"(b1))
#define CPA16(dst, src) \
    asm volatile("cp.async.cg.shared.global [%0], [%1], 16;" :: "r"(dst), "l"(src))
#define CPA_COMMIT() asm volatile("cp.async.commit_group;" ::: "memory")
#define CPA_WAIT0()  asm volatile("cp.async.wait_group 0;" ::: "memory")
#define CPA_WAIT1()  asm volatile("cp.async.wait_group 1;" ::: "memory")
#define HMUL2(out, a, b) \
    asm("mul.rn.f16x2 %0, %1, %2;" : "=r"(out) : "r"(a), "r"(b))
#define EX2H2(out, a) \
    asm("ex2.approx.f16x2 %0, %1;" : "=r"(out) : "r"(a))

__device__ __forceinline__ uint2 pack4h(float4 x) {
    half2 h0 = __floats2half2_rn(x.x, x.y);
    half2 h1 = __floats2half2_rn(x.z, x.w);
    return make_uint2(*(uint32_t*)&h0, *(uint32_t*)&h1);
}
__device__ __forceinline__ uint32_t pack2h(float a, float b) {
    half2 h = __floats2half2_rn(a, b);
    return *(uint32_t*)&h;
}

// ------- kernel 0: fused prep (K/V fp32->fp16 bh-major; tile-packed w) -----
__global__ void prep_kernel(const float* __restrict__ k, const float* __restrict__ v,
                            const float* __restrict__ wm, const float* __restrict__ tau) {
    if (blockIdx.x < 8192) {
        int o = blockIdx.x * 256 + threadIdx.x;      // half4 index, 2^21 total
        int e4 = o & 15;
        int s  = (o >> 4) & 1023;
        int bh = o >> 14;
        int b = bh >> 3, h = bh & 7;
        size_t in = (((size_t)b * L_SZ + s) * H_SZ + h) * 16 + e4;   // float4 units
        ((uint2*)g_kh)[o] = pack4h(((const float4*)k)[in]);
        ((uint2*)g_vh)[o] = pack4h(((const float4*)v)[in]);
        return;
    }
    // w modulation row -> tile-major fragment-packed fp16 layout
    __shared__ float red_m[8];
    __shared__ float red_s[8];
    const int row = blockIdx.x - 8192, tid = threadIdx.x;
    const int warp = tid >> 5, lane = tid & 31;

    float t = tau[row];
    float sp = (t > 20.f) ? t : log1pf(__expf(t));
    float inv = 1.f / sp;

    float4 x = reinterpret_cast<const float4*>(wm + (size_t)row * L_SZ)[tid];
    x.x *= inv; x.y *= inv; x.z *= inv; x.w *= inv;

    float mx = fmaxf(fmaxf(x.x, x.y), fmaxf(x.z, x.w));
    #pragma unroll
    for (int o = 16; o; o >>= 1) mx = fmaxf(mx, __shfl_xor_sync(0xffffffffu, mx, o));
    if (lane == 0) red_m[warp] = mx;
    __syncthreads();
    float M = red_m[0];
    #pragma unroll
    for (int i = 1; i < 8; i++) M = fmaxf(M, red_m[i]);

    float e0 = __expf(x.x - M), e1 = __expf(x.y - M);
    float e2 = __expf(x.z - M), e3 = __expf(x.w - M);
    float s = e0 + e1 + e2 + e3;
    #pragma unroll
    for (int o = 16; o; o >>= 1) s += __shfl_xor_sync(0xffffffffu, s, o);
    if (lane == 0) red_s[warp] = s;
    __syncthreads();
    float S = 0.f;
    #pragma unroll
    for (int i = 0; i < 8; i++) S += red_s[i];

    float f = 0.125f / S * 1.44269504089f;   // fold 1/sqrt(E) and log2(e)
    // pairs p0 = 2*tid (cols 4t..4t+1), p1 = 2*tid+1 (cols 4t+2..4t+3)
    #pragma unroll
    for (int u = 0; u < 2; u++) {
        int p = 2 * tid + u;
        uint32_t val = u ? pack2h(e2 * f, e3 * f) : pack2h(e0 * f, e1 * f);
        int st = p >> 5, p5 = p & 31;
        int t4p = p5 & 3, nb = p5 >> 2;
        g_wt[st * 32768 + (nb >> 1) * 8192 + (row * 4 + t4p) * 2 + (nb & 1)] = val;
    }
}

// -- kernel 2: fat-warp flash attention, w in smem ring, 2 CTAs/SM ----------
__global__ void __launch_bounds__(THREADS, 2)
flash_kernel(const float* __restrict__ q, float* __restrict__ out) {
    extern __shared__ char smem[];
    const uint32_t sb = smem_u32(smem);

    const int tid = threadIdx.x;
    const int warp = tid >> 5, lane = tid & 31;    // 4 M-warps, 32 rows each
    const int g = lane >> 2, t4 = lane & 3;
    const int l0 = blockIdx.x * BM;
    const int bh = blockIdx.y;

    const size_t base = (size_t)(bh >> 3) * (L_SZ * RS) + (size_t)(bh & 7) * E_SZ;
    const float* qb = q + base;
    float* ob = out + base;
    const __half* khb = g_kh + (size_t)bh * (L_SZ * E_SZ);
    const __half* vhb = g_vh + (size_t)bh * (L_SZ * E_SZ);

    // cp.async chunk assignment: K/V rows c0r + 16j; w: 4 chunks of 32B
    const int c0r = tid >> 3, c0c = (tid & 7) << 4;

    // ---- prologue: issue tiles 0 and 1 (K,V,w), stage Q ----
    #pragma unroll
    for (int t = 0; t < 2; t++) {
        const int s0 = t * BN;
        #pragma unroll
        for (int j = 0; j < 4; j++) {
            int r = c0r + 16 * j;
            CPA16(sb + KO(t) + swz(r, c0c), khb + (s0 + r) * 64 + (c0c >> 1));
            CPA16(sb + VO(t) + swz(r, c0c), vhb + (s0 + r) * 64 + (c0c >> 1));
        }
        const uint32_t* wsrc = g_wt + (size_t)t * 32768 + l0 * 8;
        #pragma unroll
        for (int nb2 = 0; nb2 < 4; nb2++) {
            CPA16(sb + WO(t) + nb2 * 4096 + tid * 32, wsrc + nb2 * 8192 + tid * 8);
            CPA16(sb + WO(t) + nb2 * 4096 + tid * 32 + 16, wsrc + nb2 * 8192 + tid * 8 + 4);
        }
        CPA_COMMIT();
    }
    #pragma unroll
    for (int i = 0; i < 16; i++) {
        int e4 = i * THREADS + tid;              // 2048 float4
        int r = e4 >> 4, c = (e4 & 15) << 2;
        float4 x = *(const float4*)(qb + (size_t)(l0 + r) * RS + c);
        *(uint2*)(smem + QO + swz(r, c * 2)) = pack4h(x);
    }
    CPA_WAIT1();        // tile 0 landed
    __syncthreads();    // Q + tile 0 visible to all warps

    // ---- persistent Q fragments (rows 32w..+31, k=0..63): 32 regs ----
    uint32_t QA[2][4][4];
    #pragma unroll
    for (int mb = 0; mb < 2; mb++)
        #pragma unroll
        for (int kbk = 0; kbk < 4; kbk++)
            LDSM4(QA[mb][kbk][0], QA[mb][kbk][1], QA[mb][kbk][2], QA[mb][kbk][3],
                  sb + QO + swz(32 * warp + 16 * mb + (lane & 15),
                                kbk * 32 + ((lane >> 4) << 4)));

    float O[2][8][4];
    #pragma unroll
    for (int mb = 0; mb < 2; mb++)
        #pragma unroll
        for (int nb = 0; nb < 8; nb++) {
            O[mb][nb][0] = 0.f; O[mb][nb][1] = 0.f; O[mb][nb][2] = 0.f; O[mb][nb][3] = 0.f;
        }
    float ls[2][2] = {{0.f, 0.f}, {0.f, 0.f}};

    for (int st = 0; st < NT; st++) {
        const int buf = st % 3;

        // issue cp.async for tile st+2 into its ring slot (read at st-1, freed)
        if (st + 2 < NT) {
            const int nb3 = (st + 2) % 3;
            const int s0n = (st + 2) * BN;
            #pragma unroll
            for (int j = 0; j < 4; j++) {
                int r = c0r + 16 * j;
                CPA16(sb + KO(nb3) + swz(r, c0c), khb + (s0n + r) * 64 + (c0c >> 1));
                CPA16(sb + VO(nb3) + swz(r, c0c), vhb + (s0n + r) * 64 + (c0c >> 1));
            }
            const uint32_t* wsrc = g_wt + (size_t)(st + 2) * 32768 + l0 * 8;
            #pragma unroll
            for (int nb2 = 0; nb2 < 4; nb2++) {
                CPA16(sb + WO(nb3) + nb2 * 4096 + tid * 32, wsrc + nb2 * 8192 + tid * 8);
                CPA16(sb + WO(nb3) + nb2 * 4096 + tid * 32 + 16, wsrc + nb2 * 8192 + tid * 8 + 4);
            }
            CPA_COMMIT();
        }

        // ---- S = Q K^T (fp16 accum): 16 LDSM4, 64 MMA (32 rows x 64 cols) --
        uint32_t S[2][8][2];
        #pragma unroll
        for (int mb = 0; mb < 2; mb++)
            #pragma unroll
            for (int nb = 0; nb < 8; nb++) { S[mb][nb][0] = 0u; S[mb][nb][1] = 0u; }
        #pragma unroll
        for (int s16 = 0; s16 < 4; s16++) {
            #pragma unroll
            for (int kbk = 0; kbk < 4; kbk++) {
                uint32_t Kf0, Kf1, Kf2, Kf3;
                int rk = s16 * 16 + (lane & 7) + ((lane & 16) >> 1);
                int cbk = kbk * 32 + (((lane >> 3) & 1) << 4);
                LDSM4(Kf0, Kf1, Kf2, Kf3, sb + KO(buf) + swz(rk, cbk));
                #pragma unroll
                for (int mb = 0; mb < 2; mb++) {
                    MMA16816H(S[mb][2 * s16],     QA[mb][kbk][0], QA[mb][kbk][1],
                              QA[mb][kbk][2], QA[mb][kbk][3], Kf0, Kf1);
                    MMA16816H(S[mb][2 * s16 + 1], QA[mb][kbk][0], QA[mb][kbk][1],
                              QA[mb][kbk][2], QA[mb][kbk][3], Kf2, Kf3);
                }
            }
        }

        // ---- softmax fp16x2: p = ex2(S_h2 * w_h2); w from smem (LDS.64) ----
        uint32_t P[2][4][4];
        #pragma unroll
        for (int mb = 0; mb < 2; mb++) {
            // load w for rows g and g+8 of this mb: 8 x LDS.64, conflict-free
            uint32_t wl[2][8];
            #pragma unroll
            for (int h = 0; h < 2; h++) {
                int rl = 32 * warp + 16 * mb + 8 * h + g;
                uint32_t wa = (uint32_t)((rl * 4 + t4) * 8);
                #pragma unroll
                for (int nb2 = 0; nb2 < 4; nb2++) {
                    uint2 wv = *(const uint2*)(smem + WO(buf) + nb2 * 4096 + wa);
                    wl[h][2 * nb2]     = wv.x;
                    wl[h][2 * nb2 + 1] = wv.y;
                }
            }
            #pragma unroll
            for (int nb = 0; nb < 8; nb++) {
                uint32_t z0, z1, p0, p1;
                HMUL2(z0, S[mb][nb][0], wl[0][nb]);   // row g
                HMUL2(z1, S[mb][nb][1], wl[1][nb]);   // row g+8
                EX2H2(p0, z0);
                EX2H2(p1, z1);
                P[mb][nb >> 1][(nb & 1) * 2]     = p0;
                P[mb][nb >> 1][(nb & 1) * 2 + 1] = p1;
                float2 f0 = __half22float2(*(half2*)&p0);
                float2 f1 = __half22float2(*(half2*)&p1);
                ls[mb][0] += f0.x + f0.y;
                ls[mb][1] += f1.x + f1.y;
            }
        }

        // ---- O += P V (fp32 accum): 16 LDSM4T, 64 MMA ----
        #pragma unroll
        for (int kb = 0; kb < 4; kb++) {
            uint32_t Vf[4][4];
            #pragma unroll
            for (int n16 = 0; n16 < 4; n16++) {
                int rv = kb * 16 + (lane & 15);
                int cbv = n16 * 32 + ((lane >> 4) << 4);
                LDSM4T(Vf[n16][0], Vf[n16][1], Vf[n16][2], Vf[n16][3],
                       sb + VO(buf) + swz(rv, cbv));
            }
            #pragma unroll
            for (int mb = 0; mb < 2; mb++)
                #pragma unroll
                for (int nb = 0; nb < 8; nb++)
                    MMA16816(O[mb][nb], P[mb][kb][0], P[mb][kb][1], P[mb][kb][2], P[mb][kb][3],
                             Vf[nb >> 1][(nb & 1) * 2], Vf[nb >> 1][(nb & 1) * 2 + 1]);
        }

        // ensure tile st+1 landed; barrier frees this iter's ring slot
        if (st < NT - 1) {
            if (st + 2 < NT) CPA_WAIT1(); else CPA_WAIT0();
            __syncthreads();
        }
    }

    // ---- epilogue: quad-reduce ls, scale, store directly ----
    #pragma unroll
    for (int mb = 0; mb < 2; mb++)
        #pragma unroll
        for (int h = 0; h < 2; h++) {
            ls[mb][h] += __shfl_xor_sync(0xffffffffu, ls[mb][h], 1);
            ls[mb][h] += __shfl_xor_sync(0xffffffffu, ls[mb][h], 2);
        }

    #pragma unroll
    for (int mb = 0; mb < 2; mb++) {
        float inv0 = 1.f / ls[mb][0];
        float inv1 = 1.f / ls[mb][1];
        int r = l0 + 32 * warp + 16 * mb + g;
        #pragma unroll
        for (int nb = 0; nb < 8; nb++) {
            int c = 8 * nb + 2 * t4;
            *(float2*)(ob + (size_t)r * RS + c) =
                make_float2(O[mb][nb][0] * inv0, O[mb][nb][1] * inv0);
            *(float2*)(ob + (size_t)(r + 8) * RS + c) =
                make_float2(O[mb][nb][2] * inv1, O[mb][nb][3] * inv1);
        }
    }
}

// ---------------- launcher ----------------
extern "C" void kernel_launch(void* const* d_in, const int* in_sizes, int n_in,
                              void* d_out, int out_size) {
    const float* q   = (const float*)d_in[0];
    const float* k   = (const float*)d_in[1];
    const float* v   = (const float*)d_in[2];
    const float* wm  = (const float*)d_in[3];
    const float* tau = (const float*)d_in[4];
    // d_in[5] = attn_mask, unused (mask_flag=False)

    cudaFuncSetAttribute(flash_kernel, cudaFuncAttributeMaxDynamicSharedMemorySize, SMEM_BYTES);

    prep_kernel<<<8192 + 1024, 256>>>(k, v, wm, tau);

    dim3 grid(L_SZ / BM, B_SZ * H_SZ);
    flash_kernel<<<grid, THREADS, SMEM_BYTES>>>(q, (float*)d_out);
}